// round 1
// baseline (speedup 1.0000x reference)
#include <cuda_runtime.h>
#include <stdint.h>
#include <math.h>

// Problem constants
#define NN   8192
#define DD   128
#define TILE 128
#define PAD  132                     // 128 + 4 pad: float4-aligned rows, 4-way-max store conflicts
#define SMEM_BYTES (2 * DD * PAD * 4)

// ---------------- device scratch (allocation-free: static globals) ----------------
__device__ double g_S;        // sum over off-diagonal of 1/w
__device__ double g_T;        // sum over off-diagonal of log w
__device__ double g_Dlog;     // sum over diagonal of log w
__device__ double g_U;        // sum over off-diagonal of sigmoid
__device__ double g_Ud;       // sum over diagonal of sigmoid
__device__ float  g_B;        // exp(log_baseline) = S / (N(N-1))
__device__ float  g_x2[NN];
__device__ float  g_y2[NN];
__device__ float  g_W[(size_t)NN * (size_t)NN];   // w = 1 + d2, 256 MiB scratch

// ---------------- fast math helpers (no MUFU: rt_MUFU=8 would bottleneck 67M ops) --
__device__ __forceinline__ float frcp_fast(float x) {
    // Bit-trick seed (~5% rel err) + 3 Newton steps -> ~1 ulp
    float r = __uint_as_float(0x7EF311C3u - __float_as_uint(x));
    r = r * fmaf(-x, r, 2.0f);
    r = r * fmaf(-x, r, 2.0f);
    r = r * fmaf(-x, r, 2.0f);
    return r;
}

__device__ __forceinline__ float flog_acc(float x) {
    // Accurate ln(x) for x >= 1 via exponent extraction + atanh series.
    // |s| <= 0.1716 -> truncation error < 1e-9; total abs err ~ 5e-7.
    uint32_t ui = __float_as_uint(x);
    int e = (int)(ui >> 23) - 127;
    float m = __uint_as_float((ui & 0x007FFFFFu) | 0x3F800000u);   // [1,2)
    if (m > 1.41421356f) { m *= 0.5f; e += 1; }                     // [0.707,1.414)
    float s  = (m - 1.0f) * frcp_fast(m + 1.0f);
    float s2 = s * s;
    float p  = fmaf(s2, 0.11111111f, 0.14285715f);   // 1/9, 1/7
    p = fmaf(s2, p, 0.2f);                            // 1/5
    p = fmaf(s2, p, 0.33333334f);                     // 1/3
    p = fmaf(s2, p, 1.0f);
    return fmaf((float)e, 0.6931471805599453f, 2.0f * s * p);
}

__device__ __forceinline__ float warp_red(float v) {
    #pragma unroll
    for (int o = 16; o; o >>= 1) v += __shfl_down_sync(0xffffffffu, v, o);
    return v;
}

// ---------------- kernels ----------------
__global__ void init_kernel() {
    g_S = 0.0; g_T = 0.0; g_Dlog = 0.0; g_U = 0.0; g_Ud = 0.0;
}

// One warp per row; 16384 rows total (X then Y).
__global__ void rowsum_kernel(const float* __restrict__ X, const float* __restrict__ Y) {
    int warps_per_block = blockDim.x >> 5;
    int row  = blockIdx.x * warps_per_block + (threadIdx.x >> 5);
    int lane = threadIdx.x & 31;
    if (row >= 2 * NN) return;
    const float* src = (row < NN) ? (X + (size_t)row * DD) : (Y + (size_t)(row - NN) * DD);
    float s = 0.0f;
    #pragma unroll
    for (int c = lane; c < DD; c += 32) { float v = src[c]; s = fmaf(v, v, s); }
    s = warp_red(s);
    if (lane == 0) {
        if (row < NN) g_x2[row] = s; else g_y2[row - NN] = s;
    }
}

// Pass 1: tiled fp32 gram (128x128 tile per CTA, full K=128 in smem, k-major),
// fused epilogue: w=1+d2, store w, accumulate S/T/Dlog.
__global__ void __launch_bounds__(256, 1)
pass1_kernel(const float* __restrict__ X, const float* __restrict__ Y) {
    extern __shared__ float sm[];
    float* Xs = sm;                  // Xs[k*PAD + m]
    float* Ys = sm + DD * PAD;       // Ys[k*PAD + n]

    const int tid  = threadIdx.x;
    const int tx   = tid & 15;
    const int ty   = tid >> 4;
    const int lane = tid & 31;
    const int w_id = tid >> 5;
    const int bx   = blockIdx.x;     // column tile (j / y)
    const int by   = blockIdx.y;     // row tile (i / x)

    // Cooperative transposed load: per task, lane = k-column, 4 consecutive rows.
    // Global: fully coalesced 128B per instr. Smem: stride PAD -> 4-way conflicts max.
    {
        const float* gX = X + (size_t)by * TILE * DD;
        const float* gY = Y + (size_t)bx * TILE * DD;
        for (int t = w_id; t < 128; t += 8) {
            int g  = t >> 5;           // column group 0..3
            int q  = t & 31;           // row quad 0..31
            int k  = g * 32 + lane;
            int r0 = q * 4;
            #pragma unroll
            for (int rr = 0; rr < 4; rr++) {
                Xs[k * PAD + r0 + rr] = gX[(size_t)(r0 + rr) * DD + k];
                Ys[k * PAD + r0 + rr] = gY[(size_t)(r0 + rr) * DD + k];
            }
        }
    }
    __syncthreads();

    float acc[8][8];
    #pragma unroll
    for (int i = 0; i < 8; i++)
        #pragma unroll
        for (int j = 0; j < 8; j++) acc[i][j] = 0.0f;

    const float* xa = Xs + ty * 8;
    const float* yb = Ys + tx * 8;

    #pragma unroll 4
    for (int k = 0; k < DD; k++) {
        float4 a0 = *(const float4*)(xa + k * PAD);
        float4 a1 = *(const float4*)(xa + k * PAD + 4);
        float4 b0 = *(const float4*)(yb + k * PAD);
        float4 b1 = *(const float4*)(yb + k * PAD + 4);
        float av[8] = {a0.x, a0.y, a0.z, a0.w, a1.x, a1.y, a1.z, a1.w};
        float bv[8] = {b0.x, b0.y, b0.z, b0.w, b1.x, b1.y, b1.z, b1.w};
        #pragma unroll
        for (int i = 0; i < 8; i++)
            #pragma unroll
            for (int j = 0; j < 8; j++)
                acc[i][j] = fmaf(av[i], bv[j], acc[i][j]);
    }

    // Epilogue
    const int gi0 = by * TILE + ty * 8;
    const int gj0 = bx * TILE + tx * 8;
    float x2v[8], y2v[8];
    #pragma unroll
    for (int i = 0; i < 8; i++) x2v[i] = g_x2[gi0 + i];
    #pragma unroll
    for (int j = 0; j < 8; j++) y2v[j] = g_y2[gj0 + j];

    float s_sum = 0.0f, t_sum = 0.0f, d_sum = 0.0f;
    #pragma unroll
    for (int i = 0; i < 8; i++) {
        float wrow[8];
        #pragma unroll
        for (int j = 0; j < 8; j++) {
            float d2 = fmaf(-2.0f, acc[i][j], x2v[i] + y2v[j]);
            d2 = fmaxf(d2, 0.0f);
            float w  = 1.0f + d2;
            wrow[j]  = w;
            float lw = flog_acc(w);
            float rw = frcp_fast(w);
            if ((gi0 + i) == (gj0 + j)) {
                d_sum += lw;
            } else {
                t_sum += lw;
                s_sum += rw;
            }
        }
        float* dst = &g_W[(size_t)(gi0 + i) * NN + gj0];
        *(float4*)(dst)     = make_float4(wrow[0], wrow[1], wrow[2], wrow[3]);
        *(float4*)(dst + 4) = make_float4(wrow[4], wrow[5], wrow[6], wrow[7]);
    }

    // Block reduction (double) + atomics
    __syncthreads();
    double* red = (double*)sm;
    s_sum = warp_red(s_sum);
    t_sum = warp_red(t_sum);
    d_sum = warp_red(d_sum);
    if (lane == 0) {
        red[w_id]      = (double)s_sum;
        red[8 + w_id]  = (double)t_sum;
        red[16 + w_id] = (double)d_sum;
    }
    __syncthreads();
    if (tid == 0) {
        double a = 0.0, b = 0.0, c = 0.0;
        #pragma unroll
        for (int i = 0; i < 8; i++) { a += red[i]; b += red[8 + i]; c += red[16 + i]; }
        atomicAdd(&g_S, a);
        atomicAdd(&g_T, b);
        if (bx == by) atomicAdd(&g_Dlog, c);
    }
}

__global__ void setB_kernel() {
    double M = (double)NN * ((double)NN - 1.0);
    g_B = (float)(g_S / M);
}

// Pass 2: sigmoid sums. HBM-bound streaming read of g_W.
__global__ void __launch_bounds__(256)
pass2_kernel() {
    const float B = g_B;
    const float4* W4 = (const float4*)g_W;
    const size_t total4 = ((size_t)NN * NN) >> 2;
    const size_t stride = (size_t)gridDim.x * blockDim.x;

    float u = 0.0f, ud = 0.0f;
    for (size_t p = (size_t)blockIdx.x * blockDim.x + threadIdx.x; p < total4; p += stride) {
        float4 w4 = W4[p];
        unsigned base = (unsigned)(p << 2);
        unsigned i  = base >> 13;     // row
        unsigned j0 = base & 8191;    // col of first element
        float vals[4] = {w4.x, w4.y, w4.z, w4.w};
        #pragma unroll
        for (int c = 0; c < 4; c++) {
            float sg = frcp_fast(fmaf(B, vals[c], 1.0f));
            if (j0 + (unsigned)c == i) ud += sg; else u += sg;
        }
    }

    __shared__ double red[16];
    int lane = threadIdx.x & 31, w_id = threadIdx.x >> 5;
    u  = warp_red(u);
    ud = warp_red(ud);
    if (lane == 0) { red[w_id] = (double)u; red[8 + w_id] = (double)ud; }
    __syncthreads();
    if (threadIdx.x == 0) {
        double a = 0.0, b = 0.0;
        #pragma unroll
        for (int i = 0; i < 8; i++) { a += red[i]; b += red[8 + i]; }
        atomicAdd(&g_U, a);
        atomicAdd(&g_Ud, b);
    }
}

__global__ void finalize_kernel(float* __restrict__ out) {
    double M = (double)NN * ((double)NN - 1.0);
    double b = log(g_S / M);                       // log_baseline
    double mean_pos = -(g_Dlog / (double)NN) - b;
    double mean_neg = -(g_T / M) - b;
    double attraction = -mean_pos;
    double repulsion  = 1.0;                        // mean(exp(neg - logmeanexp(neg))) == 1 exactly
    out[0] = (float)(attraction + repulsion);       // loss
    out[1] = (float)mean_pos;
    out[2] = (float)mean_neg;
    out[3] = (float)(g_Ud / (double)NN);            // mean sigmoid(pos)
    out[4] = (float)(g_U / M);                      // mean sigmoid(neg)
    out[5] = (float)attraction;
    out[6] = (float)repulsion;
    out[7] = (float)b;
}

// ---------------- launch ----------------
extern "C" void kernel_launch(void* const* d_in, const int* in_sizes, int n_in,
                              void* d_out, int out_size) {
    (void)in_sizes; (void)n_in; (void)out_size;
    const float* X = (const float*)d_in[0];   // context_embedding [N,D]
    const float* Y = (const float*)d_in[1];   // target_embedding  [N,D]
    float* out = (float*)d_out;

    cudaFuncSetAttribute(pass1_kernel, cudaFuncAttributeMaxDynamicSharedMemorySize, SMEM_BYTES);

    init_kernel<<<1, 1>>>();

    // row sums of squares: 2N rows, 8 warps per block
    rowsum_kernel<<<(2 * NN) / 8, 256>>>(X, Y);

    dim3 grid(NN / TILE, NN / TILE);
    pass1_kernel<<<grid, 256, SMEM_BYTES>>>(X, Y);

    setB_kernel<<<1, 1>>>();

    pass2_kernel<<<2048, 256>>>();

    finalize_kernel<<<1, 1>>>(out);
}

// round 3
// speedup vs baseline: 2.4506x; 2.4506x over previous
#include <cuda_runtime.h>
#include <cuda_fp16.h>
#include <stdint.h>
#include <math.h>

#define NN   8192
#define DD   128
#define TILE 128
#define PA   132   // smem row stride in floats: 132 % 32 == 4 -> conflict-free fragment LDS

// ---------------- device scratch ----------------
__device__ double g_S;        // sum off-diagonal of 1/w
__device__ double g_Tl;       // sum off-diagonal of log2(w)
__device__ double g_Dl;       // sum diagonal of log2(w)
__device__ double g_U;        // sum off-diagonal sigmoid
__device__ double g_Ud;       // sum diagonal sigmoid
__device__ float  g_x2[NN];
__device__ float  g_y2[NN];
__device__ __half g_Wh[(size_t)NN * (size_t)NN];   // w = 1 + d2, fp16, 128 MiB

__device__ __forceinline__ float warp_red(float v) {
    #pragma unroll
    for (int o = 16; o; o >>= 1) v += __shfl_down_sync(0xffffffffu, v, o);
    return v;
}

// tf32 mma, fp32 accum. Operands are raw fp32 bit patterns (hardware truncates to tf32).
__device__ __forceinline__ void mma_tf32(float* c, const uint32_t* a, const uint32_t* b) {
    asm volatile(
        "mma.sync.aligned.m16n8k8.row.col.f32.tf32.tf32.f32 "
        "{%0,%1,%2,%3}, {%4,%5,%6,%7}, {%8,%9}, {%0,%1,%2,%3};"
        : "+f"(c[0]), "+f"(c[1]), "+f"(c[2]), "+f"(c[3])
        : "r"(a[0]), "r"(a[1]), "r"(a[2]), "r"(a[3]), "r"(b[0]), "r"(b[1]));
}

// ---------------- small kernels ----------------
__global__ void init_kernel() { g_S = 0.0; g_Tl = 0.0; g_Dl = 0.0; g_U = 0.0; g_Ud = 0.0; }

__global__ void rowsum_kernel(const float* __restrict__ X, const float* __restrict__ Y) {
    int row  = blockIdx.x * (blockDim.x >> 5) + (threadIdx.x >> 5);
    int lane = threadIdx.x & 31;
    if (row >= 2 * NN) return;
    const float* src = (row < NN) ? (X + (size_t)row * DD) : (Y + (size_t)(row - NN) * DD);
    float s = 0.0f;
    #pragma unroll
    for (int c = lane; c < DD; c += 32) { float v = src[c]; s = fmaf(v, v, s); }
    s = warp_red(s);
    if (lane == 0) { if (row < NN) g_x2[row] = s; else g_y2[row - NN] = s; }
}

// ---------------- pass 1: tf32 mma.sync gram + fused epilogue ----------------
// smem: As[128*PA] | Bs[128*PA] | sx2[128] | sy2[128] | red[24 doubles]
#define SM_FLOATS (2 * TILE * PA + 256)
#define SMEM_P1   (SM_FLOATS * 4 + 192)

__global__ void __launch_bounds__(256, 1)
pass1_kernel(const float* __restrict__ X, const float* __restrict__ Y) {
    extern __shared__ float sm[];
    float* As  = sm;
    float* Bs  = sm + TILE * PA;
    float* sx2 = sm + 2 * TILE * PA;
    float* sy2 = sx2 + 128;
    double* red = (double*)(sm + SM_FLOATS);

    const int tid  = threadIdx.x;
    const int wid  = tid >> 5;
    const int lane = tid & 31;
    const int g    = lane >> 2;         // groupID
    const int t    = lane & 3;          // thread-in-group
    const int bx = blockIdx.x, by = blockIdx.y;
    const int gi0 = by * TILE, gj0 = bx * TILE;

    if (tid < 128) sx2[tid] = g_x2[gi0 + tid];
    else           sy2[tid - 128] = g_y2[gj0 + tid - 128];

    // cooperative tile load (fp32, row-major, pad PA). 8 rows per iter per tensor.
    {
        const float* gX = X + (size_t)gi0 * DD;
        const float* gY = Y + (size_t)gj0 * DD;
        #pragma unroll
        for (int it = 0; it < 16; it++) {
            int idx = it * 256 + tid;
            int r = idx >> 5, c4 = (idx & 31) << 2;
            *(float4*)&As[r * PA + c4] = *(const float4*)(gX + (size_t)r * DD + c4);
            *(float4*)&Bs[r * PA + c4] = *(const float4*)(gY + (size_t)r * DD + c4);
        }
    }
    __syncthreads();

    // warp tiling: 2 (m) x 4 (n) warps; each warp: 64 rows x 32 cols
    const int m0 = (wid & 1) * 64;
    const int n0 = (wid >> 1) * 32;

    float acc[4][4][4];
    #pragma unroll
    for (int mi = 0; mi < 4; mi++)
        #pragma unroll
        for (int ni = 0; ni < 4; ni++)
            #pragma unroll
            for (int c = 0; c < 4; c++) acc[mi][ni][c] = 0.0f;

    const uint32_t* Au = (const uint32_t*)As;
    const uint32_t* Bu = (const uint32_t*)Bs;

    #pragma unroll
    for (int ks = 0; ks < 16; ks++) {
        const int kb = ks * 8;
        uint32_t a[4][4], b[4][2];
        #pragma unroll
        for (int mi = 0; mi < 4; mi++) {
            int base = (m0 + mi * 16 + g) * PA + kb + t;
            a[mi][0] = Au[base];
            a[mi][1] = Au[base + 8 * PA];
            a[mi][2] = Au[base + 4];
            a[mi][3] = Au[base + 8 * PA + 4];
        }
        #pragma unroll
        for (int ni = 0; ni < 4; ni++) {
            int base = (n0 + ni * 8 + g) * PA + kb + t;
            b[ni][0] = Bu[base];
            b[ni][1] = Bu[base + 4];
        }
        #pragma unroll
        for (int mi = 0; mi < 4; mi++)
            #pragma unroll
            for (int ni = 0; ni < 4; ni++)
                mma_tf32(acc[mi][ni], a[mi], b[ni]);
    }

    // epilogue on register fragments
    const bool diag_blk = (bx == by);
    float tsum = 0.0f, ssum = 0.0f, dsum = 0.0f;

    #pragma unroll
    for (int mi = 0; mi < 4; mi++) {
        #pragma unroll
        for (int h = 0; h < 2; h++) {
            const int row = m0 + mi * 16 + g + 8 * h;
            const int gi  = gi0 + row;
            const float x2v = sx2[row];
            #pragma unroll
            for (int ni = 0; ni < 4; ni++) {
                const int col0 = n0 + ni * 8 + 2 * t;
                float c0 = acc[mi][ni][2 * h];
                float c1 = acc[mi][ni][2 * h + 1];
                float w0 = 1.0f + fmaxf(fmaf(-2.0f, c0, x2v + sy2[col0]), 0.0f);
                float w1 = 1.0f + fmaxf(fmaf(-2.0f, c1, x2v + sy2[col0 + 1]), 0.0f);
                float lg0, lg1, r0, r1;
                asm("lg2.approx.f32 %0, %1;" : "=f"(lg0) : "f"(w0));
                asm("lg2.approx.f32 %0, %1;" : "=f"(lg1) : "f"(w1));
                asm("rcp.approx.f32 %0, %1;" : "=f"(r0) : "f"(w0));
                asm("rcp.approx.f32 %0, %1;" : "=f"(r1) : "f"(w1));
                const int gj = gj0 + col0;
                if (diag_blk && gj == gi)          { dsum += lg0; tsum += lg1; ssum += r1; }
                else if (diag_blk && gj + 1 == gi) { dsum += lg1; tsum += lg0; ssum += r0; }
                else { tsum += lg0 + lg1; ssum += r0 + r1; }
                uint32_t pk;
                asm("cvt.rn.f16x2.f32 %0, %1, %2;" : "=r"(pk) : "f"(w1), "f"(w0));
                *(uint32_t*)(g_Wh + (size_t)gi * NN + gj) = pk;
            }
        }
    }

    // block reduction (double) + atomics
    tsum = warp_red(tsum); ssum = warp_red(ssum); dsum = warp_red(dsum);
    if (lane == 0) {
        red[wid] = (double)ssum; red[8 + wid] = (double)tsum; red[16 + wid] = (double)dsum;
    }
    __syncthreads();
    if (tid == 0) {
        double a = 0, bb = 0, cc = 0;
        #pragma unroll
        for (int i = 0; i < 8; i++) { a += red[i]; bb += red[8 + i]; cc += red[16 + i]; }
        atomicAdd(&g_S, a);
        atomicAdd(&g_Tl, bb);
        if (diag_blk) atomicAdd(&g_Dl, cc);
    }
}

// ---------------- pass 2: sigmoid sums (fp16 W stream) ----------------
__global__ void __launch_bounds__(256)
pass2_kernel() {
    const double M = (double)NN * ((double)NN - 1.0);
    const float B = (float)(g_S / M);
    const uint4* W8 = (const uint4*)g_Wh;          // 8 halves per uint4
    const size_t total8 = ((size_t)NN * NN) >> 3;
    const size_t stride = (size_t)gridDim.x * blockDim.x;

    float u = 0.0f, ud = 0.0f;
    for (size_t p = (size_t)blockIdx.x * blockDim.x + threadIdx.x; p < total8; p += stride) {
        uint4 q = W8[p];
        uint32_t uw[4] = { q.x, q.y, q.z, q.w };
        size_t base = p << 3;
        unsigned i  = (unsigned)(base >> 13);
        unsigned j0 = (unsigned)(base & 8191);
        #pragma unroll
        for (int k = 0; k < 4; k++) {
            __half2 h2 = *reinterpret_cast<__half2*>(&uw[k]);
            float2 f = __half22float2(h2);
            float s0, s1;
            asm("rcp.approx.f32 %0, %1;" : "=f"(s0) : "f"(fmaf(B, f.x, 1.0f)));
            asm("rcp.approx.f32 %0, %1;" : "=f"(s1) : "f"(fmaf(B, f.y, 1.0f)));
            unsigned j = j0 + 2 * k;
            if (j == i)          { ud += s0; u += s1; }
            else if (j + 1 == i) { ud += s1; u += s0; }
            else                 { u += s0 + s1; }
        }
    }

    __shared__ double red[16];
    int lane = threadIdx.x & 31, w_id = threadIdx.x >> 5;
    u = warp_red(u); ud = warp_red(ud);
    if (lane == 0) { red[w_id] = (double)u; red[8 + w_id] = (double)ud; }
    __syncthreads();
    if (threadIdx.x == 0) {
        double a = 0, bb = 0;
        #pragma unroll
        for (int i = 0; i < 8; i++) { a += red[i]; bb += red[8 + i]; }
        atomicAdd(&g_U, a);
        atomicAdd(&g_Ud, bb);
    }
}

__global__ void finalize_kernel(float* __restrict__ out) {
    const double LN2 = 0.6931471805599453;
    double M = (double)NN * ((double)NN - 1.0);
    double b = log(g_S / M);
    double mean_pos = -(g_Dl * LN2 / (double)NN) - b;
    double mean_neg = -(g_Tl * LN2 / M) - b;
    double attraction = -mean_pos;
    double repulsion  = 1.0;   // mean(exp(neg - logmeanexp(neg))) == 1 exactly
    out[0] = (float)(attraction + repulsion);
    out[1] = (float)mean_pos;
    out[2] = (float)mean_neg;
    out[3] = (float)(g_Ud / (double)NN);
    out[4] = (float)(g_U / M);
    out[5] = (float)attraction;
    out[6] = (float)repulsion;
    out[7] = (float)b;
}

// ---------------- launch ----------------
extern "C" void kernel_launch(void* const* d_in, const int* in_sizes, int n_in,
                              void* d_out, int out_size) {
    (void)in_sizes; (void)n_in; (void)out_size;
    const float* X = (const float*)d_in[0];
    const float* Y = (const float*)d_in[1];
    float* out = (float*)d_out;

    cudaFuncSetAttribute(pass1_kernel, cudaFuncAttributeMaxDynamicSharedMemorySize, SMEM_P1);

    init_kernel<<<1, 1>>>();
    rowsum_kernel<<<(2 * NN) / 8, 256>>>(X, Y);

    dim3 grid(NN / TILE, NN / TILE);
    pass1_kernel<<<grid, 256, SMEM_P1>>>(X, Y);

    pass2_kernel<<<2048, 256>>>();
    finalize_kernel<<<1, 1>>>(out);
}

// round 4
// speedup vs baseline: 3.8186x; 1.5583x over previous
#include <cuda_runtime.h>
#include <cuda_fp16.h>
#include <stdint.h>
#include <math.h>

#define NN   8192
#define DD   128
#define TILE 128
#define PAH  136   // smem row pitch in halves (272B = 17*16B -> ldmatrix conflict-free)

// ---------------- device scratch ----------------
__device__ double g_S;        // sum off-diagonal of 1/w
__device__ double g_Tl;       // sum off-diagonal of log2(w)
__device__ double g_Dl;       // sum diagonal of log2(w)
__device__ double g_U;        // sum over ALL elements of sigmoid
__device__ double g_Ud;       // sum over diagonal of sigmoid
__device__ float  g_x2[NN];
__device__ float  g_y2[NN];
__device__ __half g_Wh[(size_t)NN * (size_t)NN];   // w = 1 + d2, fp16, 128 MiB

__device__ __forceinline__ float warp_red(float v) {
    #pragma unroll
    for (int o = 16; o; o >>= 1) v += __shfl_down_sync(0xffffffffu, v, o);
    return v;
}

__device__ __forceinline__ uint32_t smem_u32(const void* p) {
    uint32_t a;
    asm("{ .reg .u64 t; cvta.to.shared.u64 t, %1; cvt.u32.u64 %0, t; }" : "=r"(a) : "l"(p));
    return a;
}

__device__ __forceinline__ void ldsm_x4(uint32_t& r0, uint32_t& r1, uint32_t& r2, uint32_t& r3,
                                        uint32_t addr) {
    asm volatile("ldmatrix.sync.aligned.m8n8.x4.shared.b16 {%0,%1,%2,%3}, [%4];"
        : "=r"(r0), "=r"(r1), "=r"(r2), "=r"(r3) : "r"(addr));
}

// fp16 mma, fp32 accum
__device__ __forceinline__ void mma_f16(float* c, const uint32_t* a, const uint32_t* b) {
    asm volatile(
        "mma.sync.aligned.m16n8k16.row.col.f32.f16.f16.f32 "
        "{%0,%1,%2,%3}, {%4,%5,%6,%7}, {%8,%9}, {%0,%1,%2,%3};"
        : "+f"(c[0]), "+f"(c[1]), "+f"(c[2]), "+f"(c[3])
        : "r"(a[0]), "r"(a[1]), "r"(a[2]), "r"(a[3]), "r"(b[0]), "r"(b[1]));
}

// ---------------- small kernels ----------------
__global__ void init_kernel() { g_S = 0.0; g_Tl = 0.0; g_Dl = 0.0; g_U = 0.0; g_Ud = 0.0; }

__global__ void rowsum_kernel(const float* __restrict__ X, const float* __restrict__ Y) {
    int row  = blockIdx.x * (blockDim.x >> 5) + (threadIdx.x >> 5);
    int lane = threadIdx.x & 31;
    if (row >= 2 * NN) return;
    const float* src = (row < NN) ? (X + (size_t)row * DD) : (Y + (size_t)(row - NN) * DD);
    float s = 0.0f;
    #pragma unroll
    for (int c = lane; c < DD; c += 32) { float v = src[c]; s = fmaf(v, v, s); }
    s = warp_red(s);
    if (lane == 0) { if (row < NN) g_x2[row] = s; else g_y2[row - NN] = s; }
}

// ---------------- pass 1: fp16 mma.sync gram + fused epilogue ----------------
// smem bytes: As[128*PAH*2]=34816 | Bs same | sx2 512 | sy2 512 | red 192  -> ~70.9KB, occ 2
#define AS_BYTES (TILE * PAH * 2)
#define OFF_BS   AS_BYTES
#define OFF_SX2  (2 * AS_BYTES)
#define OFF_SY2  (OFF_SX2 + 512)
#define OFF_RED  (OFF_SY2 + 512)
#define SMEM_P1  (OFF_RED + 192)

__global__ void __launch_bounds__(256, 2)
pass1_kernel(const float* __restrict__ X, const float* __restrict__ Y) {
    extern __shared__ char smem[];
    __half* As  = (__half*)smem;
    __half* Bs  = (__half*)(smem + OFF_BS);
    float*  sx2 = (float*)(smem + OFF_SX2);
    float*  sy2 = (float*)(smem + OFF_SY2);
    double* red = (double*)(smem + OFF_RED);

    const int tid  = threadIdx.x;
    const int wid  = tid >> 5;
    const int lane = tid & 31;
    const int g    = lane >> 2;         // groupID
    const int t    = lane & 3;          // thread-in-group
    const int bx = blockIdx.x, by = blockIdx.y;
    const int gi0 = by * TILE, gj0 = bx * TILE;

    if (tid < 128) sx2[tid] = g_x2[gi0 + tid];
    else           sy2[tid - 128] = g_y2[gj0 + tid - 128];

    // cooperative tile load: fp32 -> half (RN) -> padded smem
    {
        const float* gX = X + (size_t)gi0 * DD;
        const float* gY = Y + (size_t)gj0 * DD;
        #pragma unroll
        for (int it = 0; it < 16; it++) {
            int idx = it * 256 + tid;
            int r = idx >> 5, c4 = (idx & 31) << 2;
            float4 vx = *(const float4*)(gX + (size_t)r * DD + c4);
            float4 vy = *(const float4*)(gY + (size_t)r * DD + c4);
            __half2 x01 = __floats2half2_rn(vx.x, vx.y);
            __half2 x23 = __floats2half2_rn(vx.z, vx.w);
            __half2 y01 = __floats2half2_rn(vy.x, vy.y);
            __half2 y23 = __floats2half2_rn(vy.z, vy.w);
            *(uint2*)(As + r * PAH + c4) =
                make_uint2(*(uint32_t*)&x01, *(uint32_t*)&x23);
            *(uint2*)(Bs + r * PAH + c4) =
                make_uint2(*(uint32_t*)&y01, *(uint32_t*)&y23);
        }
    }
    __syncthreads();

    // warp tiling: 2 (m) x 4 (n) warps; each warp: 64 rows x 32 cols
    const int m0 = (wid & 1) * 64;
    const int n0 = (wid >> 1) * 32;

    // per-lane ldmatrix base addresses (bytes)
    const uint32_t as_b = smem_u32(As);
    const uint32_t bs_b = smem_u32(Bs);
    const int mat   = lane >> 3;
    const int mrow  = lane & 7;
    uint32_t a_addr[4], b_addr[2];
    #pragma unroll
    for (int mi = 0; mi < 4; mi++) {
        int row  = m0 + mi * 16 + (mat & 1) * 8 + mrow;
        int koff = (mat >> 1) * 8;
        a_addr[mi] = as_b + (row * PAH + koff) * 2;
    }
    #pragma unroll
    for (int p = 0; p < 2; p++) {
        int n    = n0 + p * 16 + (mat >> 1) * 8 + mrow;
        int koff = (mat & 1) * 8;
        b_addr[p] = bs_b + (n * PAH + koff) * 2;
    }

    float acc[4][4][4];
    #pragma unroll
    for (int mi = 0; mi < 4; mi++)
        #pragma unroll
        for (int ni = 0; ni < 4; ni++)
            #pragma unroll
            for (int c = 0; c < 4; c++) acc[mi][ni][c] = 0.0f;

    #pragma unroll
    for (int ks = 0; ks < 8; ks++) {
        uint32_t a[4][4], b[4][2];
        #pragma unroll
        for (int mi = 0; mi < 4; mi++)
            ldsm_x4(a[mi][0], a[mi][1], a[mi][2], a[mi][3], a_addr[mi] + ks * 32);
        ldsm_x4(b[0][0], b[0][1], b[1][0], b[1][1], b_addr[0] + ks * 32);
        ldsm_x4(b[2][0], b[2][1], b[3][0], b[3][1], b_addr[1] + ks * 32);
        #pragma unroll
        for (int mi = 0; mi < 4; mi++)
            #pragma unroll
            for (int ni = 0; ni < 4; ni++)
                mma_f16(acc[mi][ni], a[mi], b[ni]);
    }

    // epilogue on register fragments
    const bool diag_blk = (bx == by);
    float tsum = 0.0f, ssum = 0.0f, dsum = 0.0f;

    #pragma unroll
    for (int mi = 0; mi < 4; mi++) {
        #pragma unroll
        for (int h = 0; h < 2; h++) {
            const int row = m0 + mi * 16 + g + 8 * h;
            const int gi  = gi0 + row;
            const float x2v = sx2[row];
            #pragma unroll
            for (int ni = 0; ni < 4; ni++) {
                const int col0 = n0 + ni * 8 + 2 * t;
                float c0 = acc[mi][ni][2 * h];
                float c1 = acc[mi][ni][2 * h + 1];
                float w0 = 1.0f + fmaxf(fmaf(-2.0f, c0, x2v + sy2[col0]), 0.0f);
                float w1 = 1.0f + fmaxf(fmaf(-2.0f, c1, x2v + sy2[col0 + 1]), 0.0f);
                float lg0, lg1, r0, r1;
                asm("lg2.approx.f32 %0, %1;" : "=f"(lg0) : "f"(w0));
                asm("lg2.approx.f32 %0, %1;" : "=f"(lg1) : "f"(w1));
                asm("rcp.approx.f32 %0, %1;" : "=f"(r0) : "f"(w0));
                asm("rcp.approx.f32 %0, %1;" : "=f"(r1) : "f"(w1));
                const int gj = gj0 + col0;
                if (diag_blk && gj == gi)          { dsum += lg0; tsum += lg1; ssum += r1; }
                else if (diag_blk && gj + 1 == gi) { dsum += lg1; tsum += lg0; ssum += r0; }
                else { tsum += lg0 + lg1; ssum += r0 + r1; }
                uint32_t pk;
                asm("cvt.rn.f16x2.f32 %0, %1, %2;" : "=r"(pk) : "f"(w1), "f"(w0));
                *(uint32_t*)(g_Wh + (size_t)gi * NN + gj) = pk;
            }
        }
    }

    // block reduction (double) + atomics
    tsum = warp_red(tsum); ssum = warp_red(ssum); dsum = warp_red(dsum);
    if (lane == 0) {
        red[wid] = (double)ssum; red[8 + wid] = (double)tsum; red[16 + wid] = (double)dsum;
    }
    __syncthreads();
    if (tid == 0) {
        double a = 0, bb = 0, cc = 0;
        #pragma unroll
        for (int i = 0; i < 8; i++) { a += red[i]; bb += red[8 + i]; cc += red[16 + i]; }
        atomicAdd(&g_S, a);
        atomicAdd(&g_Tl, bb);
        if (diag_blk) atomicAdd(&g_Dl, cc);
    }
}

// ---------------- diagonal sigmoid (tiny) ----------------
__global__ void diag_kernel() {
    const double M = (double)NN * ((double)NN - 1.0);
    const float B = (float)(g_S / M);
    int i = blockIdx.x * blockDim.x + threadIdx.x;
    float w = __half2float(g_Wh[(size_t)i * NN + i]);
    float s;
    asm("rcp.approx.f32 %0, %1;" : "=f"(s) : "f"(fmaf(B, w, 1.0f)));
    s = warp_red(s);
    __shared__ double red[8];
    int lane = threadIdx.x & 31, w_id = threadIdx.x >> 5;
    if (lane == 0) red[w_id] = (double)s;
    __syncthreads();
    if (threadIdx.x == 0) {
        double a = 0;
        #pragma unroll
        for (int k = 0; k < 8; k++) a += red[k];
        atomicAdd(&g_Ud, a);
    }
}

// ---------------- pass 2: branch-free sigmoid sum over ALL elements ----------------
__global__ void __launch_bounds__(256)
pass2_kernel() {
    const double M = (double)NN * ((double)NN - 1.0);
    const float B = (float)(g_S / M);
    const uint4* W8 = (const uint4*)g_Wh;          // 8 halves per uint4
    const size_t total8 = ((size_t)NN * NN) >> 3;
    const size_t stride = (size_t)gridDim.x * blockDim.x;

    float u = 0.0f;
    for (size_t p = (size_t)blockIdx.x * blockDim.x + threadIdx.x; p < total8; p += stride) {
        uint4 q = W8[p];
        uint32_t uw[4] = { q.x, q.y, q.z, q.w };
        #pragma unroll
        for (int k = 0; k < 4; k++) {
            float2 f = __half22float2(*reinterpret_cast<__half2*>(&uw[k]));
            float s0, s1;
            asm("rcp.approx.f32 %0, %1;" : "=f"(s0) : "f"(fmaf(B, f.x, 1.0f)));
            asm("rcp.approx.f32 %0, %1;" : "=f"(s1) : "f"(fmaf(B, f.y, 1.0f)));
            u += s0 + s1;
        }
    }

    __shared__ double red[8];
    int lane = threadIdx.x & 31, w_id = threadIdx.x >> 5;
    u = warp_red(u);
    if (lane == 0) red[w_id] = (double)u;
    __syncthreads();
    if (threadIdx.x == 0) {
        double a = 0;
        #pragma unroll
        for (int i = 0; i < 8; i++) a += red[i];
        atomicAdd(&g_U, a);
    }
}

__global__ void finalize_kernel(float* __restrict__ out) {
    const double LN2 = 0.6931471805599453;
    double M = (double)NN * ((double)NN - 1.0);
    double b = log(g_S / M);
    double mean_pos = -(g_Dl * LN2 / (double)NN) - b;
    double mean_neg = -(g_Tl * LN2 / M) - b;
    double attraction = -mean_pos;
    double repulsion  = 1.0;   // mean(exp(neg - logmeanexp(neg))) == 1 exactly
    out[0] = (float)(attraction + repulsion);
    out[1] = (float)mean_pos;
    out[2] = (float)mean_neg;
    out[3] = (float)(g_Ud / (double)NN);
    out[4] = (float)((g_U - g_Ud) / M);    // U included diagonal; remove it
    out[5] = (float)attraction;
    out[6] = (float)repulsion;
    out[7] = (float)b;
}

// ---------------- launch ----------------
extern "C" void kernel_launch(void* const* d_in, const int* in_sizes, int n_in,
                              void* d_out, int out_size) {
    (void)in_sizes; (void)n_in; (void)out_size;
    const float* X = (const float*)d_in[0];
    const float* Y = (const float*)d_in[1];
    float* out = (float*)d_out;

    cudaFuncSetAttribute(pass1_kernel, cudaFuncAttributeMaxDynamicSharedMemorySize, SMEM_P1);

    init_kernel<<<1, 1>>>();
    rowsum_kernel<<<(2 * NN) / 8, 256>>>(X, Y);

    dim3 grid(NN / TILE, NN / TILE);
    pass1_kernel<<<grid, 256, SMEM_P1>>>(X, Y);

    diag_kernel<<<NN / 256, 256>>>();
    pass2_kernel<<<2048, 256>>>();
    finalize_kernel<<<1, 1>>>(out);
}

// round 5
// speedup vs baseline: 4.3644x; 1.1429x over previous
#include <cuda_runtime.h>
#include <cuda_fp16.h>
#include <stdint.h>
#include <math.h>

#define NN   8192
#define DD   128
#define TILE 128
#define PAH  136   // smem row pitch in halves (272B = 17*16B -> ldmatrix conflict-free)

// ---------------- device scratch ----------------
__device__ double g_S;        // sum off-diagonal of 1/w
__device__ double g_Tl;       // sum off-diagonal of log2(w)
__device__ double g_Dl;       // sum diagonal of log2(w)
__device__ double g_U;        // sum over ALL elements of sigmoid
__device__ double g_Ud;       // sum over diagonal of sigmoid
__device__ float  g_x2[NN];
__device__ float  g_y2[NN];
__device__ __half g_Wh[(size_t)NN * (size_t)NN];   // w = 1 + d2, fp16, 128 MiB

__device__ __forceinline__ float warp_red(float v) {
    #pragma unroll
    for (int o = 16; o; o >>= 1) v += __shfl_down_sync(0xffffffffu, v, o);
    return v;
}

__device__ __forceinline__ uint32_t smem_u32(const void* p) {
    uint32_t a;
    asm("{ .reg .u64 t; cvta.to.shared.u64 t, %1; cvt.u32.u64 %0, t; }" : "=r"(a) : "l"(p));
    return a;
}

__device__ __forceinline__ void ldsm_x4(uint32_t& r0, uint32_t& r1, uint32_t& r2, uint32_t& r3,
                                        uint32_t addr) {
    asm volatile("ldmatrix.sync.aligned.m8n8.x4.shared.b16 {%0,%1,%2,%3}, [%4];"
        : "=r"(r0), "=r"(r1), "=r"(r2), "=r"(r3) : "r"(addr));
}

// fp16 mma, fp32 accum
__device__ __forceinline__ void mma_f16(float* c, const uint32_t* a, const uint32_t* b) {
    asm volatile(
        "mma.sync.aligned.m16n8k16.row.col.f32.f16.f16.f32 "
        "{%0,%1,%2,%3}, {%4,%5,%6,%7}, {%8,%9}, {%0,%1,%2,%3};"
        : "+f"(c[0]), "+f"(c[1]), "+f"(c[2]), "+f"(c[3])
        : "r"(a[0]), "r"(a[1]), "r"(a[2]), "r"(a[3]), "r"(b[0]), "r"(b[1]));
}

__device__ __forceinline__ float mrcp(float x) {
    float r; asm("rcp.approx.f32 %0, %1;" : "=f"(r) : "f"(x)); return r;
}
__device__ __forceinline__ float mlg2(float x) {
    float r; asm("lg2.approx.f32 %0, %1;" : "=f"(r) : "f"(x)); return r;
}

// ---------------- rowsum (+ init of accumulators) ----------------
__global__ void rowsum_kernel(const float* __restrict__ X, const float* __restrict__ Y) {
    if (blockIdx.x == 0 && threadIdx.x == 0) {
        g_S = 0.0; g_Tl = 0.0; g_Dl = 0.0; g_U = 0.0; g_Ud = 0.0;
    }
    int row  = blockIdx.x * (blockDim.x >> 5) + (threadIdx.x >> 5);
    int lane = threadIdx.x & 31;
    if (row >= 2 * NN) return;
    const float* src = (row < NN) ? (X + (size_t)row * DD) : (Y + (size_t)(row - NN) * DD);
    float s = 0.0f;
    #pragma unroll
    for (int c = lane; c < DD; c += 32) { float v = src[c]; s = fmaf(v, v, s); }
    s = warp_red(s);
    if (lane == 0) { if (row < NN) g_x2[row] = s; else g_y2[row - NN] = s; }
}

// ---------------- pass 1: fp16 mma.sync gram + fused epilogue ----------------
// smem bytes: As[128*PAH*2]=34816 | Bs same | sx2 512 | sy2p 512 | red 192  -> ~70.9KB, occ 2
#define AS_BYTES (TILE * PAH * 2)
#define OFF_BS   AS_BYTES
#define OFF_SX2  (2 * AS_BYTES)
#define OFF_SY2  (OFF_SX2 + 512)
#define OFF_RED  (OFF_SY2 + 512)
#define SMEM_P1  (OFF_RED + 192)

__global__ void __launch_bounds__(256, 2)
pass1_kernel(const float* __restrict__ X, const float* __restrict__ Y) {
    extern __shared__ char smem[];
    __half* As   = (__half*)smem;
    __half* Bs   = (__half*)(smem + OFF_BS);
    float*  sx2  = (float*)(smem + OFF_SX2);
    float*  sy2p = (float*)(smem + OFF_SY2);   // y2 + 1.0
    double* red  = (double*)(smem + OFF_RED);

    const int tid  = threadIdx.x;
    const int wid  = tid >> 5;
    const int lane = tid & 31;
    const int g    = lane >> 2;         // groupID
    const int t    = lane & 3;          // thread-in-group
    const int bx = blockIdx.x, by = blockIdx.y;
    const int gi0 = by * TILE, gj0 = bx * TILE;

    if (tid < 128) sx2[tid] = g_x2[gi0 + tid];
    else           sy2p[tid - 128] = g_y2[gj0 + tid - 128] + 1.0f;

    // cooperative tile load: fp32 -> half (RN) -> padded smem
    {
        const float* gX = X + (size_t)gi0 * DD;
        const float* gY = Y + (size_t)gj0 * DD;
        #pragma unroll
        for (int it = 0; it < 16; it++) {
            int idx = it * 256 + tid;
            int r = idx >> 5, c4 = (idx & 31) << 2;
            float4 vx = *(const float4*)(gX + (size_t)r * DD + c4);
            float4 vy = *(const float4*)(gY + (size_t)r * DD + c4);
            __half2 x01 = __floats2half2_rn(vx.x, vx.y);
            __half2 x23 = __floats2half2_rn(vx.z, vx.w);
            __half2 y01 = __floats2half2_rn(vy.x, vy.y);
            __half2 y23 = __floats2half2_rn(vy.z, vy.w);
            *(uint2*)(As + r * PAH + c4) = make_uint2(*(uint32_t*)&x01, *(uint32_t*)&x23);
            *(uint2*)(Bs + r * PAH + c4) = make_uint2(*(uint32_t*)&y01, *(uint32_t*)&y23);
        }
    }
    __syncthreads();

    // warp tiling: 2 (m) x 4 (n) warps; each warp: 64 rows x 32 cols
    const int m0 = (wid & 1) * 64;
    const int n0 = (wid >> 1) * 32;

    const uint32_t as_b = smem_u32(As);
    const uint32_t bs_b = smem_u32(Bs);
    const int mat  = lane >> 3;
    const int mrow = lane & 7;
    uint32_t a_addr[4], b_addr[2];
    #pragma unroll
    for (int mi = 0; mi < 4; mi++) {
        int row  = m0 + mi * 16 + (mat & 1) * 8 + mrow;
        int koff = (mat >> 1) * 8;
        a_addr[mi] = as_b + (row * PAH + koff) * 2;
    }
    #pragma unroll
    for (int p = 0; p < 2; p++) {
        int n    = n0 + p * 16 + (mat >> 1) * 8 + mrow;
        int koff = (mat & 1) * 8;
        b_addr[p] = bs_b + (n * PAH + koff) * 2;
    }

    float acc[4][4][4];
    #pragma unroll
    for (int mi = 0; mi < 4; mi++)
        #pragma unroll
        for (int ni = 0; ni < 4; ni++)
            #pragma unroll
            for (int c = 0; c < 4; c++) acc[mi][ni][c] = 0.0f;

    #pragma unroll
    for (int ks = 0; ks < 8; ks++) {
        uint32_t a[4][4], b[4][2];
        #pragma unroll
        for (int mi = 0; mi < 4; mi++)
            ldsm_x4(a[mi][0], a[mi][1], a[mi][2], a[mi][3], a_addr[mi] + ks * 32);
        ldsm_x4(b[0][0], b[0][1], b[1][0], b[1][1], b_addr[0] + ks * 32);
        ldsm_x4(b[2][0], b[2][1], b[3][0], b[3][1], b_addr[1] + ks * 32);
        #pragma unroll
        for (int mi = 0; mi < 4; mi++)
            #pragma unroll
            for (int ni = 0; ni < 4; ni++)
                mma_f16(acc[mi][ni], a[mi], b[ni]);
    }

    const bool diag_blk = (bx == by);
    float tsum = 0.0f, ssum = 0.0f, dsum = 0.0f;

    if (!diag_blk) {
        // fast path: batched MUFU. Per (mi,h): 8 elements -> 1 lg2 + 4 rcp.
        #pragma unroll
        for (int mi = 0; mi < 4; mi++) {
            #pragma unroll
            for (int h = 0; h < 2; h++) {
                const int row = m0 + mi * 16 + g + 8 * h;
                const int gi  = gi0 + row;
                const float x2v = sx2[row];
                float w[8];
                #pragma unroll
                for (int ni = 0; ni < 4; ni++) {
                    const int col0 = n0 + ni * 8 + 2 * t;
                    float c0 = acc[mi][ni][2 * h];
                    float c1 = acc[mi][ni][2 * h + 1];
                    // w = 1 + max(d2,0) = max(fma(-2c, x2+y2+1), 1)
                    float w0 = fmaxf(fmaf(-2.0f, c0, x2v + sy2p[col0]), 1.0f);
                    float w1 = fmaxf(fmaf(-2.0f, c1, x2v + sy2p[col0 + 1]), 1.0f);
                    w[2 * ni] = w0; w[2 * ni + 1] = w1;
                    uint32_t pk;
                    asm("cvt.rn.f16x2.f32 %0, %1, %2;" : "=r"(pk) : "f"(w1), "f"(w0));
                    *(uint32_t*)(g_Wh + (size_t)gi * NN + gj0 + col0) = pk;
                }
                float p01 = w[0] * w[1], p23 = w[2] * w[3];
                float p45 = w[4] * w[5], p67 = w[6] * w[7];
                float q0 = p01 * p23, q1 = p45 * p67;
                tsum += mlg2(q0 * q1);                       // sum of 8 logs
                ssum = fmaf(w[0] + w[1], mrcp(p01), ssum);   // pairs of reciprocals
                ssum = fmaf(w[2] + w[3], mrcp(p23), ssum);
                ssum = fmaf(w[4] + w[5], mrcp(p45), ssum);
                ssum = fmaf(w[6] + w[7], mrcp(p67), ssum);
            }
        }
    } else {
        // slow path (64 CTAs): per-element, exact diagonal split
        #pragma unroll
        for (int mi = 0; mi < 4; mi++) {
            #pragma unroll
            for (int h = 0; h < 2; h++) {
                const int row = m0 + mi * 16 + g + 8 * h;
                const int gi  = gi0 + row;
                const float x2v = sx2[row];
                #pragma unroll
                for (int ni = 0; ni < 4; ni++) {
                    const int col0 = n0 + ni * 8 + 2 * t;
                    float c0 = acc[mi][ni][2 * h];
                    float c1 = acc[mi][ni][2 * h + 1];
                    float w0 = fmaxf(fmaf(-2.0f, c0, x2v + sy2p[col0]), 1.0f);
                    float w1 = fmaxf(fmaf(-2.0f, c1, x2v + sy2p[col0 + 1]), 1.0f);
                    float lg0 = mlg2(w0), lg1 = mlg2(w1);
                    float r0 = mrcp(w0),  r1 = mrcp(w1);
                    const int gj = gj0 + col0;
                    if (gj == gi)          { dsum += lg0; tsum += lg1; ssum += r1; }
                    else if (gj + 1 == gi) { dsum += lg1; tsum += lg0; ssum += r0; }
                    else { tsum += lg0 + lg1; ssum += r0 + r1; }
                    uint32_t pk;
                    asm("cvt.rn.f16x2.f32 %0, %1, %2;" : "=r"(pk) : "f"(w1), "f"(w0));
                    *(uint32_t*)(g_Wh + (size_t)gi * NN + gj) = pk;
                }
            }
        }
    }

    // block reduction (double) + atomics
    tsum = warp_red(tsum); ssum = warp_red(ssum); dsum = warp_red(dsum);
    if (lane == 0) {
        red[wid] = (double)ssum; red[8 + wid] = (double)tsum; red[16 + wid] = (double)dsum;
    }
    __syncthreads();
    if (tid == 0) {
        double a = 0, bb = 0, cc = 0;
        #pragma unroll
        for (int i = 0; i < 8; i++) { a += red[i]; bb += red[8 + i]; cc += red[16 + i]; }
        atomicAdd(&g_S, a);
        atomicAdd(&g_Tl, bb);
        if (diag_blk) atomicAdd(&g_Dl, cc);
    }
}

// ---------------- pass 2: sigmoid sums over ALL elements + diagonal ----------------
__global__ void __launch_bounds__(256)
pass2_kernel() {
    const double M = (double)NN * ((double)NN - 1.0);
    const float B = (float)(g_S / M);
    const uint4* W8 = (const uint4*)g_Wh;          // 8 halves per uint4
    const size_t total8 = ((size_t)NN * NN) >> 3;
    const size_t stride = (size_t)gridDim.x * blockDim.x;

    float u = 0.0f, ud = 0.0f;
    for (size_t p = (size_t)blockIdx.x * blockDim.x + threadIdx.x; p < total8; p += stride) {
        uint4 q = W8[p];
        uint32_t uw[4] = { q.x, q.y, q.z, q.w };
        #pragma unroll
        for (int k = 0; k < 4; k += 2) {
            float2 f0 = __half22float2(*reinterpret_cast<__half2*>(&uw[k]));
            float2 f1 = __half22float2(*reinterpret_cast<__half2*>(&uw[k + 1]));
            float a0 = fmaf(B, f0.x, 1.0f), a1 = fmaf(B, f0.y, 1.0f);
            float a2 = fmaf(B, f1.x, 1.0f), a3 = fmaf(B, f1.y, 1.0f);
            u = fmaf(a0 + a1, mrcp(a0 * a1), u);   // 1/a0 + 1/a1
            u = fmaf(a2 + a3, mrcp(a2 * a3), u);
        }
    }

    // block 0: diagonal sigmoids (8192 strided loads, hidden behind the stream)
    if (blockIdx.x == 0) {
        for (int i = threadIdx.x; i < NN; i += 256) {
            float w = __half2float(g_Wh[(size_t)i * NN + i]);
            ud += mrcp(fmaf(B, w, 1.0f));
        }
    }

    __shared__ double red[16];
    int lane = threadIdx.x & 31, w_id = threadIdx.x >> 5;
    u = warp_red(u); ud = warp_red(ud);
    if (lane == 0) { red[w_id] = (double)u; red[8 + w_id] = (double)ud; }
    __syncthreads();
    if (threadIdx.x == 0) {
        double a = 0, bb = 0;
        #pragma unroll
        for (int i = 0; i < 8; i++) { a += red[i]; bb += red[8 + i]; }
        atomicAdd(&g_U, a);
        if (blockIdx.x == 0) atomicAdd(&g_Ud, bb);
    }
}

__global__ void finalize_kernel(float* __restrict__ out) {
    const double LN2 = 0.6931471805599453;
    double M = (double)NN * ((double)NN - 1.0);
    double b = log(g_S / M);
    double mean_pos = -(g_Dl * LN2 / (double)NN) - b;
    double mean_neg = -(g_Tl * LN2 / M) - b;
    double attraction = -mean_pos;
    double repulsion  = 1.0;   // mean(exp(neg - logmeanexp(neg))) == 1 exactly
    out[0] = (float)(attraction + repulsion);
    out[1] = (float)mean_pos;
    out[2] = (float)mean_neg;
    out[3] = (float)(g_Ud / (double)NN);
    out[4] = (float)((g_U - g_Ud) / M);    // U included diagonal; remove it
    out[5] = (float)attraction;
    out[6] = (float)repulsion;
    out[7] = (float)b;
}

// ---------------- launch ----------------
extern "C" void kernel_launch(void* const* d_in, const int* in_sizes, int n_in,
                              void* d_out, int out_size) {
    (void)in_sizes; (void)n_in; (void)out_size;
    const float* X = (const float*)d_in[0];
    const float* Y = (const float*)d_in[1];
    float* out = (float*)d_out;

    cudaFuncSetAttribute(pass1_kernel, cudaFuncAttributeMaxDynamicSharedMemorySize, SMEM_P1);

    rowsum_kernel<<<(2 * NN) / 8, 256>>>(X, Y);

    dim3 grid(NN / TILE, NN / TILE);
    pass1_kernel<<<grid, 256, SMEM_P1>>>(X, Y);

    pass2_kernel<<<2048, 256>>>();
    finalize_kernel<<<1, 1>>>(out);
}